// round 1
// baseline (speedup 1.0000x reference)
#include <cuda_runtime.h>
#include <math.h>

// Problem constants
#define C_IN   200     // real input channels (201..255 are zero-padded, skipped)
#define T_LEN  1024
#define MDIM   512     // model_dim (output slice width)
#define WC     256     // W's in-channel dim (stride)
// Tiling
#define TM     64      // m per CTA
#define TT     256     // t per CTA
#define KC     8       // channels per K-chunk (200 = 25 * 8)

// exact GELU (matches jax.nn.gelu approximate=False / torch default)
__device__ __forceinline__ float gelu_exact(float z) {
    return 0.5f * z * (1.0f + erff(z * 0.70710678118654752f));
}

__global__ __launch_bounds__(256, 2)
void dsproj_kernel(const float* __restrict__ x,
                   const int*   __restrict__ did_arr,
                   const float* __restrict__ W,
                   const float* __restrict__ bias,
                   float* __restrict__ out)
{
    // x tile with halo: rows padded to 260 floats so every row base is 16B-aligned
    __shared__ float xs[KC][TT + 4];
    __shared__ float ws[TM][KC * 3];

    const int tx  = threadIdx.x;          // 0..31  -> t
    const int ty  = threadIdx.y;          // 0..7   -> m
    const int tid = ty * 32 + tx;

    const int t0  = blockIdx.x * TT;
    const int m0  = blockIdx.y * TM;
    const int bb  = blockIdx.z;
    const int did = did_arr[bb];

    const float* xb = x + (size_t)bb * C_IN * T_LEN;
    const float* Wb = W + ((size_t)did * MDIM + m0) * (WC * 3);

    float acc[8][8];
    #pragma unroll
    for (int i = 0; i < 8; i++)
        #pragma unroll
        for (int j = 0; j < 8; j++) acc[i][j] = 0.0f;

    const int tl = tx * 8;  // local t base for this thread (covers tl..tl+7)

    for (int c0 = 0; c0 < C_IN; c0 += KC) {
        // ---- load x tile [KC][TT+2] (halo left/right by 1) ----
        #pragma unroll 1
        for (int idx = tid; idx < KC * (TT + 2); idx += 256) {
            int c = idx / (TT + 2);
            int i = idx % (TT + 2);
            int gt = t0 - 1 + i;
            float v = 0.0f;
            if (gt >= 0 && gt < T_LEN) v = xb[(c0 + c) * T_LEN + gt];
            xs[c][i] = v;
        }
        // ---- load W tile [TM][KC*3] (contiguous 24 floats per row) ----
        #pragma unroll 1
        for (int idx = tid; idx < TM * 24; idx += 256) {
            int m = idx / 24;
            int r = idx % 24;
            ws[m][r] = Wb[m * (WC * 3) + c0 * 3 + r];
        }
        __syncthreads();

        // ---- compute ----
        #pragma unroll
        for (int c = 0; c < KC; c++) {
            float xv[10];
            float4 a  = *(const float4*)&xs[c][tl];
            float4 bq = *(const float4*)&xs[c][tl + 4];
            float2 cq = *(const float2*)&xs[c][tl + 8];
            xv[0]=a.x;  xv[1]=a.y;  xv[2]=a.z;  xv[3]=a.w;
            xv[4]=bq.x; xv[5]=bq.y; xv[6]=bq.z; xv[7]=bq.w;
            xv[8]=cq.x; xv[9]=cq.y;

            #pragma unroll
            for (int i = 0; i < 8; i++) {
                const int m = ty * 8 + i;
                const float w0 = ws[m][c*3 + 0];
                const float w1 = ws[m][c*3 + 1];
                const float w2 = ws[m][c*3 + 2];
                #pragma unroll
                for (int j = 0; j < 8; j++) {
                    acc[i][j] = fmaf(w0, xv[j],     acc[i][j]);
                    acc[i][j] = fmaf(w1, xv[j + 1], acc[i][j]);
                    acc[i][j] = fmaf(w2, xv[j + 2], acc[i][j]);
                }
            }
        }
        __syncthreads();
    }

    // ---- epilogue: bias + exact GELU, float4 stores ----
    const float* brow = bias + (size_t)did * MDIM + m0;
    #pragma unroll
    for (int i = 0; i < 8; i++) {
        const int m = ty * 8 + i;
        const float bv = brow[m];
        float* orow = out + ((size_t)bb * MDIM + m0 + m) * T_LEN + t0 + tl;
        #pragma unroll
        for (int j = 0; j < 8; j += 4) {
            float4 o;
            o.x = gelu_exact(acc[i][j + 0] + bv);
            o.y = gelu_exact(acc[i][j + 1] + bv);
            o.z = gelu_exact(acc[i][j + 2] + bv);
            o.w = gelu_exact(acc[i][j + 3] + bv);
            *(float4*)&orow[j] = o;
        }
    }
}

extern "C" void kernel_launch(void* const* d_in, const int* in_sizes, int n_in,
                              void* d_out, int out_size)
{
    const float* x    = (const float*)d_in[0];   // [32, 200, 1024]
    const int*   did  = (const int*)  d_in[1];   // [32]
    const float* W    = (const float*)d_in[2];   // [4096, 256, 3]
    const float* bias = (const float*)d_in[3];   // [4096]
    float*       out  = (float*)d_out;           // [32, 512, 1024]

    dim3 grid(T_LEN / TT, MDIM / TM, 32);        // (4, 8, 32)
    dim3 block(32, 8);
    dsproj_kernel<<<grid, block>>>(x, did, W, bias, out);
}

// round 3
// speedup vs baseline: 2.5611x; 2.5611x over previous
#include <cuda_runtime.h>
#include <cuda_bf16.h>
#include <math.h>
#include <stdint.h>

// ---------------- problem constants ----------------
#define NCH   200
#define TLEN  1024
#define MD    512
#define NB    32
#define KPAD  608          // 600 real (200ch*3taps) + 8 zeros = 19 chunks of 32

// ---------------- tiling ----------------
#define TILE_M 128
#define TILE_N 128
#define KCH    32
#define NCHUNK (KPAD / KCH)        // 19
#define NSTAGE 3
#define RS     40                  // smem row stride in halfs (80B, 16B-aligned, LDSM conflict-free)
#define MAT_H  (128 * RS)          // halfs per matrix tile in one stage
#define AH_O   0
#define AL_O   (MAT_H)
#define BH_O   (2 * MAT_H)
#define BL_O   (3 * MAT_H)
#define STAGE_BYTES (4 * MAT_H * 2)        // 40960
#define SMEM_TOTAL  (NSTAGE * STAGE_BYTES) // 122880

// ---------------- device scratch (bss) ----------------
__device__ __nv_bfloat16 g_Ahi[4096 * KPAD];
__device__ __nv_bfloat16 g_Alo[4096 * KPAD];
__device__ __nv_bfloat16 g_Bhi[(size_t)NB * TLEN * KPAD];
__device__ __nv_bfloat16 g_Blo[(size_t)NB * TLEN * KPAD];

// ---------------- PTX helpers (all baseline sm_80/90 PTX, compute_103-safe) ----------------
__device__ __forceinline__ uint32_t s2u(const void* p) {
    uint32_t a;
    asm("{ .reg .u64 t; cvta.to.shared.u64 t, %1; cvt.u32.u64 %0, t; }" : "=r"(a) : "l"(p));
    return a;
}
#define CPASYNC16(dst, src) \
    asm volatile("cp.async.cg.shared.global [%0], [%1], 16;" :: "r"(dst), "l"(src) : "memory")
#define CP_COMMIT() asm volatile("cp.async.commit_group;" ::: "memory")
#define CP_WAIT(n)  asm volatile("cp.async.wait_group %0;" :: "n"(n) : "memory")

__device__ __forceinline__ void ldsm_x4(uint32_t* r, uint32_t addr) {
    asm volatile("ldmatrix.sync.aligned.m8n8.x4.shared.b16 {%0,%1,%2,%3}, [%4];"
        : "=r"(r[0]), "=r"(r[1]), "=r"(r[2]), "=r"(r[3]) : "r"(addr));
}
__device__ __forceinline__ void ldsm_x2(uint32_t* r, uint32_t addr) {
    asm volatile("ldmatrix.sync.aligned.m8n8.x2.shared.b16 {%0,%1}, [%2];"
        : "=r"(r[0]), "=r"(r[1]) : "r"(addr));
}
__device__ __forceinline__ void mma16816(float* c, const uint32_t* a, const uint32_t* b) {
    asm volatile("mma.sync.aligned.m16n8k16.row.col.f32.bf16.bf16.f32 "
        "{%0,%1,%2,%3}, {%4,%5,%6,%7}, {%8,%9}, {%0,%1,%2,%3};"
        : "+f"(c[0]), "+f"(c[1]), "+f"(c[2]), "+f"(c[3])
        : "r"(a[0]), "r"(a[1]), "r"(a[2]), "r"(a[3]), "r"(b[0]), "r"(b[1]));
}

__device__ __forceinline__ float gelu_exact(float z) {
    return 0.5f * z * (1.0f + erff(z * 0.70710678118654752f));
}

// ---------------- prep kernels ----------------
__global__ void prep_w(const float* __restrict__ W) {
    int idx = blockIdx.x * 256 + threadIdx.x;          // < 4096*608
    int m = idx / KPAD, k = idx - m * KPAD;
    // GEMM K-index c*3+kk equals flattened W[m][c][kk] for k<600 (W row = 256*3 floats)
    float v = (k < 600) ? W[m * 768 + k] : 0.0f;
    __nv_bfloat16 h = __float2bfloat16(v);
    g_Ahi[idx] = h;
    g_Alo[idx] = __float2bfloat16(v - __bfloat162float(h));
}

__global__ void prep_x(const float* __restrict__ x) {
    __shared__ float xs[50][132];
    const int b = blockIdx.y, t0 = blockIdx.x * 128;
    const int tid = threadIdx.x;
    const float* xb = x + (size_t)b * NCH * TLEN;
    const size_t Bbase = ((size_t)b * TLEN + t0) * KPAD;

    // zero K tail [600,608)
    for (int i = tid; i < 128 * 8; i += 256) {
        int tl = i >> 3, k = 600 + (i & 7);
        size_t o = Bbase + (size_t)tl * KPAD + k;
        g_Bhi[o] = __float2bfloat16(0.0f);
        g_Blo[o] = __float2bfloat16(0.0f);
    }

    for (int cc = 0; cc < 4; cc++) {
        const int c0 = cc * 50;
        __syncthreads();
        for (int i = tid; i < 50 * 130; i += 256) {
            int r = i / 130, col = i - r * 130;
            int gt = t0 - 1 + col;
            xs[r][col] = (gt >= 0 && gt < TLEN) ? xb[(size_t)(c0 + r) * TLEN + gt] : 0.0f;
        }
        __syncthreads();
        for (int i = tid; i < 128 * 150; i += 256) {
            int tl = i / 150, dk = i - tl * 150;
            int cl = dk / 3, kk = dk - cl * 3;
            float v = xs[cl][tl + kk];
            __nv_bfloat16 h = __float2bfloat16(v);
            size_t o = Bbase + (size_t)tl * KPAD + (c0 * 3 + dk);
            g_Bhi[o] = h;
            g_Blo[o] = __float2bfloat16(v - __bfloat162float(h));
        }
    }
}

// ---------------- stage copy: 4 matrices x 128 rows x 64B ----------------
__device__ __forceinline__ void copy_stage(uint32_t sb,
        const __nv_bfloat16* __restrict__ Ah, const __nv_bfloat16* __restrict__ Al,
        const __nv_bfloat16* __restrict__ Bh, const __nv_bfloat16* __restrict__ Bl,
        int k0, int tid) {
    #pragma unroll
    for (int i = 0; i < 2; i++) {
        int v = tid + i * 256;                 // 0..511
        int row = v >> 2, seg = v & 3;
        uint32_t so = row * (RS * 2) + seg * 16;
        size_t g = (size_t)row * KPAD + k0 + seg * 8;
        CPASYNC16(sb + AH_O * 2 + so, Ah + g);
        CPASYNC16(sb + AL_O * 2 + so, Al + g);
        CPASYNC16(sb + BH_O * 2 + so, Bh + g);
        CPASYNC16(sb + BL_O * 2 + so, Bl + g);
    }
}

// ---------------- main HMMA kernel ----------------
__global__ __launch_bounds__(256, 1)
void dsmain(const int* __restrict__ did_arr,
            const float* __restrict__ bias,
            float* __restrict__ out) {
    extern __shared__ __nv_bfloat16 sm[];
    const uint32_t sbase = s2u(sm);
    const int tid = threadIdx.x, wid = tid >> 5, lane = tid & 31;
    const int wm = wid >> 2, wn = wid & 3;     // warp grid 2(m) x 4(n)
    const int t0 = blockIdx.x * TILE_N, m0 = blockIdx.y * TILE_M, b = blockIdx.z;
    const int did = did_arr[b];

    const __nv_bfloat16* Ah = g_Ahi + (size_t)(did * MD + m0) * KPAD;
    const __nv_bfloat16* Al = g_Alo + (size_t)(did * MD + m0) * KPAD;
    const __nv_bfloat16* Bh = g_Bhi + ((size_t)b * TLEN + t0) * KPAD;
    const __nv_bfloat16* Bl = g_Blo + ((size_t)b * TLEN + t0) * KPAD;

    // per-lane ldmatrix byte offsets (within a matrix tile)
    uint32_t a_off[4], b_off[4];
    {
        int tl = lane >> 3, sub = lane & 7;
        int koff = (tl >> 1) * 8;
        int mrow = wm * 64 + (tl & 1) * 8 + sub;
        #pragma unroll
        for (int mt = 0; mt < 4; mt++)
            a_off[mt] = ((mrow + mt * 16) * RS + koff) * 2;
        int l = lane & 15;
        int bk = (l >> 3) * 8;
        int nrow = wn * 32 + (l & 7);
        #pragma unroll
        for (int nt = 0; nt < 4; nt++)
            b_off[nt] = ((nrow + nt * 8) * RS + bk) * 2;
    }

    float acc[4][4][4];
    #pragma unroll
    for (int i = 0; i < 4; i++)
        #pragma unroll
        for (int j = 0; j < 4; j++)
            #pragma unroll
            for (int q = 0; q < 4; q++) acc[i][j][q] = 0.0f;

    // prologue: fill 3 stages
    #pragma unroll
    for (int s = 0; s < NSTAGE; s++) {
        copy_stage(sbase + s * STAGE_BYTES, Ah, Al, Bh, Bl, s * KCH, tid);
        CP_COMMIT();
    }

    int sidx = 0;
    for (int c = 0; c < NCHUNK; c++) {
        if (c == NCHUNK - 1)      { CP_WAIT(0); }
        else if (c == NCHUNK - 2) { CP_WAIT(1); }
        else                      { CP_WAIT(2); }
        __syncthreads();

        const uint32_t sb = sbase + sidx * STAGE_BYTES;
        #pragma unroll
        for (int ks = 0; ks < 2; ks++) {
            const uint32_t kb = ks * 32;      // 16 halfs
            uint32_t ah[4][4], al[4][4], bh[4][2], bl[4][2];
            #pragma unroll
            for (int nt = 0; nt < 4; nt++) {
                ldsm_x2(bh[nt], sb + BH_O * 2 + b_off[nt] + kb);
                ldsm_x2(bl[nt], sb + BL_O * 2 + b_off[nt] + kb);
            }
            #pragma unroll
            for (int mt = 0; mt < 4; mt++) {
                ldsm_x4(ah[mt], sb + AH_O * 2 + a_off[mt] + kb);
                ldsm_x4(al[mt], sb + AL_O * 2 + a_off[mt] + kb);
            }
            #pragma unroll
            for (int mt = 0; mt < 4; mt++)
                #pragma unroll
                for (int nt = 0; nt < 4; nt++) {
                    mma16816(acc[mt][nt], ah[mt], bh[nt]);
                    mma16816(acc[mt][nt], ah[mt], bl[nt]);
                    mma16816(acc[mt][nt], al[mt], bh[nt]);
                }
        }
        __syncthreads();

        if (c + NSTAGE < NCHUNK) {
            copy_stage(sb, Ah, Al, Bh, Bl, (c + NSTAGE) * KCH, tid);
            CP_COMMIT();
        }
        sidx = (sidx == NSTAGE - 1) ? 0 : sidx + 1;
    }

    // ---- epilogue: bias + exact GELU ----
    const float* brow = bias + did * MD + m0 + wm * 64;
    const int rsub = lane >> 2;
    const int csub = (lane & 3) * 2;
    #pragma unroll
    for (int mt = 0; mt < 4; mt++) {
        const float bv0 = brow[mt * 16 + rsub];
        const float bv1 = brow[mt * 16 + rsub + 8];
        float* o0 = out + ((size_t)(b * MD + m0 + wm * 64 + mt * 16 + rsub)) * TLEN
                        + t0 + wn * 32 + csub;
        float* o1 = o0 + 8 * TLEN;
        #pragma unroll
        for (int nt = 0; nt < 4; nt++) {
            float2 p0, p1;
            p0.x = gelu_exact(acc[mt][nt][0] + bv0);
            p0.y = gelu_exact(acc[mt][nt][1] + bv0);
            p1.x = gelu_exact(acc[mt][nt][2] + bv1);
            p1.y = gelu_exact(acc[mt][nt][3] + bv1);
            *(float2*)(o0 + nt * 8) = p0;
            *(float2*)(o1 + nt * 8) = p1;
        }
    }
}

// ---------------- launch ----------------
extern "C" void kernel_launch(void* const* d_in, const int* in_sizes, int n_in,
                              void* d_out, int out_size) {
    const float* x    = (const float*)d_in[0];   // [32, 200, 1024]
    const int*   did  = (const int*)  d_in[1];   // [32]
    const float* W    = (const float*)d_in[2];   // [4096, 256, 3]
    const float* bias = (const float*)d_in[3];   // [4096]
    float*       out  = (float*)d_out;           // [32, 512, 1024]

    cudaFuncSetAttribute(dsmain, cudaFuncAttributeMaxDynamicSharedMemorySize, SMEM_TOTAL);

    prep_w<<<(4096 * KPAD) / 256, 256>>>(W);
    prep_x<<<dim3(TLEN / 128, NB), 256>>>(x);
    dsmain<<<dim3(TLEN / TILE_N, MD / TILE_M, NB), 256, SMEM_TOTAL>>>(did, bias, out);
}

// round 4
// speedup vs baseline: 3.0185x; 1.1786x over previous
#include <cuda_runtime.h>
#include <cuda_bf16.h>
#include <math.h>
#include <stdint.h>

// ---------------- problem constants ----------------
#define NCH   200
#define TLEN  1024
#define MD    512
#define NB    32
#define KPAD  608          // 600 real (200ch*3taps) + 8 zeros = 19 chunks of 32

// ---------------- tiling ----------------
#define TILE_M 128
#define TILE_N 128
#define KCH    32
#define NCHUNK (KPAD / KCH)        // 19
#define NSTAGE 2
#define RS     40                  // smem row stride in halfs (80B, conflict-free for LDSM)
#define MAT_H  (128 * RS)          // halfs per matrix tile per stage (5120)
#define AH_O   0
#define AL_O   (MAT_H)
#define BH_O   (2 * MAT_H)
#define BL_O   (3 * MAT_H)
#define STAGE_BYTES (4 * MAT_H * 2)        // 40960
#define SMEM_TOTAL  (NSTAGE * STAGE_BYTES) // 81920 -> 2 CTAs/SM

// ---------------- device scratch (bss) ----------------
__device__ __nv_bfloat16 g_Ahi[4096 * KPAD];
__device__ __nv_bfloat16 g_Alo[4096 * KPAD];
__device__ __nv_bfloat16 g_Bhi[(size_t)NB * TLEN * KPAD];
__device__ __nv_bfloat16 g_Blo[(size_t)NB * TLEN * KPAD];

// ---------------- PTX helpers (baseline PTX, compute_103-safe) ----------------
__device__ __forceinline__ uint32_t s2u(const void* p) {
    uint32_t a;
    asm("{ .reg .u64 t; cvta.to.shared.u64 t, %1; cvt.u32.u64 %0, t; }" : "=r"(a) : "l"(p));
    return a;
}
#define CPASYNC16(dst, src) \
    asm volatile("cp.async.cg.shared.global [%0], [%1], 16;" :: "r"(dst), "l"(src) : "memory")
#define CP_COMMIT() asm volatile("cp.async.commit_group;" ::: "memory")
#define CP_WAIT(n)  asm volatile("cp.async.wait_group %0;" :: "n"(n) : "memory")

__device__ __forceinline__ void ldsm_x4(uint32_t* r, uint32_t addr) {
    asm volatile("ldmatrix.sync.aligned.m8n8.x4.shared.b16 {%0,%1,%2,%3}, [%4];"
        : "=r"(r[0]), "=r"(r[1]), "=r"(r[2]), "=r"(r[3]) : "r"(addr));
}
__device__ __forceinline__ void mma16816(float* c, const uint32_t* a, const uint32_t* b) {
    asm volatile("mma.sync.aligned.m16n8k16.row.col.f32.bf16.bf16.f32 "
        "{%0,%1,%2,%3}, {%4,%5,%6,%7}, {%8,%9}, {%0,%1,%2,%3};"
        : "+f"(c[0]), "+f"(c[1]), "+f"(c[2]), "+f"(c[3])
        : "r"(a[0]), "r"(a[1]), "r"(a[2]), "r"(a[3]), "r"(b[0]), "r"(b[1]));
}
__device__ __forceinline__ float gelu_exact(float z) {
    return 0.5f * z * (1.0f + erff(z * 0.70710678118654752f));
}

// ---------------- prep kernels ----------------
__global__ void prep_w(const float* __restrict__ W) {
    int p = blockIdx.x * 256 + threadIdx.x;            // pair index < 4096*304
    int idx = p * 2;
    int m = idx / KPAD, k = idx - m * KPAD;
    // GEMM K-index c*3+kk equals flattened W[m][c][kk] for k<600 (W row = 256*3 floats)
    float v0 = (k     < 600) ? W[m * 768 + k]     : 0.0f;
    float v1 = (k + 1 < 600) ? W[m * 768 + k + 1] : 0.0f;
    __nv_bfloat16 h0 = __float2bfloat16(v0);
    __nv_bfloat16 h1 = __float2bfloat16(v1);
    __nv_bfloat162 hh; hh.x = h0; hh.y = h1;
    __nv_bfloat162 ll;
    ll.x = __float2bfloat16(v0 - __bfloat162float(h0));
    ll.y = __float2bfloat16(v1 - __bfloat162float(h1));
    *(__nv_bfloat162*)&g_Ahi[idx] = hh;
    *(__nv_bfloat162*)&g_Alo[idx] = ll;
}

__global__ void prep_x(const float* __restrict__ x) {
    __shared__ float xs[50][132];
    const int b = blockIdx.y, t0 = blockIdx.x * 128;
    const int tid = threadIdx.x;
    const float* xb = x + (size_t)b * NCH * TLEN;
    const size_t Bbase = ((size_t)b * TLEN + t0) * KPAD;

    // zero K tail [600,608) — paired stores
    const __nv_bfloat162 z2 = { __float2bfloat16(0.0f), __float2bfloat16(0.0f) };
    for (int i = tid; i < 128 * 4; i += 256) {
        int tl = i >> 2, k = 600 + (i & 3) * 2;
        size_t o = Bbase + (size_t)tl * KPAD + k;
        *(__nv_bfloat162*)&g_Bhi[o] = z2;
        *(__nv_bfloat162*)&g_Blo[o] = z2;
    }

    for (int cc = 0; cc < 4; cc++) {
        const int c0 = cc * 50;
        __syncthreads();
        for (int i = tid; i < 50 * 130; i += 256) {
            int r = i / 130, col = i - r * 130;
            int gt = t0 - 1 + col;
            xs[r][col] = (gt >= 0 && gt < TLEN) ? xb[(size_t)(c0 + r) * TLEN + gt] : 0.0f;
        }
        __syncthreads();
        // 150 K-values per t -> 75 pairs, paired 4B stores (o is even)
        for (int i = tid; i < 128 * 75; i += 256) {
            int tl = i / 75, j = i - tl * 75;
            int dk0 = 2 * j;
            int cl0 = dk0 / 3,       kk0 = dk0 - cl0 * 3;
            int cl1 = (dk0 + 1) / 3, kk1 = (dk0 + 1) - cl1 * 3;
            float v0 = xs[cl0][tl + kk0];
            float v1 = xs[cl1][tl + kk1];
            __nv_bfloat16 h0 = __float2bfloat16(v0);
            __nv_bfloat16 h1 = __float2bfloat16(v1);
            __nv_bfloat162 hh; hh.x = h0; hh.y = h1;
            __nv_bfloat162 ll;
            ll.x = __float2bfloat16(v0 - __bfloat162float(h0));
            ll.y = __float2bfloat16(v1 - __bfloat162float(h1));
            size_t o = Bbase + (size_t)tl * KPAD + (c0 * 3 + dk0);
            *(__nv_bfloat162*)&g_Bhi[o] = hh;
            *(__nv_bfloat162*)&g_Blo[o] = ll;
        }
    }
}

// ---------------- stage copy: 4 matrices x 128 rows x 64B ----------------
__device__ __forceinline__ void copy_stage(uint32_t sb,
        const __nv_bfloat16* __restrict__ Ah, const __nv_bfloat16* __restrict__ Al,
        const __nv_bfloat16* __restrict__ Bh, const __nv_bfloat16* __restrict__ Bl,
        int k0, int tid) {
    #pragma unroll
    for (int i = 0; i < 2; i++) {
        int v = tid + i * 256;                 // 0..511
        int row = v >> 2, seg = v & 3;
        uint32_t so = row * (RS * 2) + seg * 16;
        size_t g = (size_t)row * KPAD + k0 + seg * 8;
        CPASYNC16(sb + AH_O * 2 + so, Ah + g);
        CPASYNC16(sb + AL_O * 2 + so, Al + g);
        CPASYNC16(sb + BH_O * 2 + so, Bh + g);
        CPASYNC16(sb + BL_O * 2 + so, Bl + g);
    }
}

// ---------------- main HMMA kernel ----------------
__global__ __launch_bounds__(256, 2)
void dsmain(const int* __restrict__ did_arr,
            const float* __restrict__ bias,
            float* __restrict__ out) {
    extern __shared__ __nv_bfloat16 sm[];
    const uint32_t sbase = s2u(sm);
    const int tid = threadIdx.x, wid = tid >> 5, lane = tid & 31;
    const int wm = wid >> 2, wn = wid & 3;     // warp grid 2(m) x 4(n)
    const int t0 = blockIdx.x * TILE_N, m0 = blockIdx.y * TILE_M, b = blockIdx.z;
    const int did = did_arr[b];

    const __nv_bfloat16* Ah = g_Ahi + (size_t)(did * MD + m0) * KPAD;
    const __nv_bfloat16* Al = g_Alo + (size_t)(did * MD + m0) * KPAD;
    const __nv_bfloat16* Bh = g_Bhi + ((size_t)b * TLEN + t0) * KPAD;
    const __nv_bfloat16* Bl = g_Blo + ((size_t)b * TLEN + t0) * KPAD;

    // per-lane ldmatrix byte offsets (within one matrix tile)
    uint32_t a_off[4], b_off[2];
    {
        // A x4: groups (lane>>3): (k0,m0-7),(k0,m8-15),(k8,m0-7),(k8,m8-15)
        int tl = lane >> 3, sub = lane & 7;
        int koff = (tl >> 1) * 8;
        int mrow = wm * 64 + (tl & 1) * 8 + sub;
        #pragma unroll
        for (int mt = 0; mt < 4; mt++)
            a_off[mt] = ((mrow + mt * 16) * RS + koff) * 2;
        // B x4 over two n8 tiles: groups: (n0-7,k0),(n0-7,k8),(n8-15,k0),(n8-15,k8)
        int g = lane >> 3;
        int nr = wn * 32 + (lane & 7) + ((g >> 1) * 8);
        int kk = (g & 1) * 8;
        #pragma unroll
        for (int p = 0; p < 2; p++)
            b_off[p] = ((nr + p * 16) * RS + kk) * 2;
    }

    float acc[4][4][4];
    #pragma unroll
    for (int i = 0; i < 4; i++)
        #pragma unroll
        for (int j = 0; j < 4; j++)
            #pragma unroll
            for (int q = 0; q < 4; q++) acc[i][j][q] = 0.0f;

    // prologue: fill both stages
    copy_stage(sbase,               Ah, Al, Bh, Bl, 0,   tid); CP_COMMIT();
    copy_stage(sbase + STAGE_BYTES, Ah, Al, Bh, Bl, KCH, tid); CP_COMMIT();

    for (int c = 0; c < NCHUNK; c++) {
        if (c < NCHUNK - 1) { CP_WAIT(1); } else { CP_WAIT(0); }
        __syncthreads();

        const uint32_t sb = sbase + (c & 1) * STAGE_BYTES;
        #pragma unroll
        for (int ks = 0; ks < 2; ks++) {
            const uint32_t kb = ks * 32;      // +16 halfs
            uint32_t bh[2][4], bl[2][4], af[4][4];
            #pragma unroll
            for (int p = 0; p < 2; p++) {
                ldsm_x4(bh[p], sb + BH_O * 2 + b_off[p] + kb);
                ldsm_x4(bl[p], sb + BL_O * 2 + b_off[p] + kb);
            }
            #pragma unroll
            for (int mt = 0; mt < 4; mt++)
                ldsm_x4(af[mt], sb + AH_O * 2 + a_off[mt] + kb);
            #pragma unroll
            for (int mt = 0; mt < 4; mt++)
                #pragma unroll
                for (int nt = 0; nt < 4; nt++) {
                    mma16816(acc[mt][nt], af[mt], &bh[nt >> 1][(nt & 1) * 2]);
                    mma16816(acc[mt][nt], af[mt], &bl[nt >> 1][(nt & 1) * 2]);
                }
            #pragma unroll
            for (int mt = 0; mt < 4; mt++)
                ldsm_x4(af[mt], sb + AL_O * 2 + a_off[mt] + kb);   // reuse regs
            #pragma unroll
            for (int mt = 0; mt < 4; mt++)
                #pragma unroll
                for (int nt = 0; nt < 4; nt++)
                    mma16816(acc[mt][nt], af[mt], &bh[nt >> 1][(nt & 1) * 2]);
        }
        __syncthreads();

        if (c + NSTAGE < NCHUNK) {
            copy_stage(sb, Ah, Al, Bh, Bl, (c + NSTAGE) * KCH, tid);
            CP_COMMIT();
        }
    }

    // ---- epilogue: bias + exact GELU ----
    const float* brow = bias + did * MD + m0 + wm * 64;
    const int rsub = lane >> 2;
    const int csub = (lane & 3) * 2;
    #pragma unroll
    for (int mt = 0; mt < 4; mt++) {
        const float bv0 = brow[mt * 16 + rsub];
        const float bv1 = brow[mt * 16 + rsub + 8];
        float* o0 = out + ((size_t)(b * MD + m0 + wm * 64 + mt * 16 + rsub)) * TLEN
                        + t0 + wn * 32 + csub;
        float* o1 = o0 + 8 * TLEN;
        #pragma unroll
        for (int nt = 0; nt < 4; nt++) {
            float2 p0, p1;
            p0.x = gelu_exact(acc[mt][nt][0] + bv0);
            p0.y = gelu_exact(acc[mt][nt][1] + bv0);
            p1.x = gelu_exact(acc[mt][nt][2] + bv1);
            p1.y = gelu_exact(acc[mt][nt][3] + bv1);
            *(float2*)(o0 + nt * 8) = p0;
            *(float2*)(o1 + nt * 8) = p1;
        }
    }
}

// ---------------- launch ----------------
extern "C" void kernel_launch(void* const* d_in, const int* in_sizes, int n_in,
                              void* d_out, int out_size) {
    const float* x    = (const float*)d_in[0];   // [32, 200, 1024]
    const int*   did  = (const int*)  d_in[1];   // [32]
    const float* W    = (const float*)d_in[2];   // [4096, 256, 3]
    const float* bias = (const float*)d_in[3];   // [4096]
    float*       out  = (float*)d_out;           // [32, 512, 1024]

    cudaFuncSetAttribute(dsmain, cudaFuncAttributeMaxDynamicSharedMemorySize, SMEM_TOTAL);

    prep_w<<<(4096 * KPAD / 2) / 256, 256>>>(W);
    prep_x<<<dim3(TLEN / 128, NB), 256>>>(x);
    dsmain<<<dim3(TLEN / TILE_N, MD / TILE_M, NB), 256, SMEM_TOTAL>>>(did, bias, out);
}

// round 5
// speedup vs baseline: 3.8734x; 1.2832x over previous
#include <cuda_runtime.h>
#include <cuda_fp16.h>
#include <math.h>
#include <stdint.h>

// ---------------- problem constants ----------------
#define NCH   200
#define TLEN  1024
#define MD    512
#define NB    32
#define KPAD  608          // 600 real (200ch*3taps) + 8 zeros = 19 chunks of 32

// ---------------- tiling ----------------
#define TILE_M 128
#define TILE_N 128
#define KCH    32
#define NCHUNK (KPAD / KCH)        // 19
#define NSTAGE 3
#define RS     40                  // smem row stride in halfs (80B, LDSM conflict-free)
#define MAT_B  (128 * RS * 2)      // bytes per matrix tile per stage (10240)
#define AH_O   0
#define AL_O   MAT_B
#define B_O    (2 * MAT_B)
#define STAGE_BYTES (3 * MAT_B)            // 30720
#define SMEM_TOTAL  (NSTAGE * STAGE_BYTES) // 92160 -> 2 CTAs/SM

// ---------------- device scratch (bss) ----------------
__device__ __half g_Ahi[4096 * KPAD];
__device__ __half g_Alo[4096 * KPAD];
__device__ __half g_Bh[(size_t)NB * TLEN * KPAD];

// ---------------- PTX helpers (baseline PTX, compute_103-safe) ----------------
__device__ __forceinline__ uint32_t s2u(const void* p) {
    uint32_t a;
    asm("{ .reg .u64 t; cvta.to.shared.u64 t, %1; cvt.u32.u64 %0, t; }" : "=r"(a) : "l"(p));
    return a;
}
#define CPASYNC16(dst, src) \
    asm volatile("cp.async.cg.shared.global [%0], [%1], 16;" :: "r"(dst), "l"(src) : "memory")
#define CP_COMMIT() asm volatile("cp.async.commit_group;" ::: "memory")
#define CP_WAIT(n)  asm volatile("cp.async.wait_group %0;" :: "n"(n) : "memory")

__device__ __forceinline__ void ldsm_x4(uint32_t* r, uint32_t addr) {
    asm volatile("ldmatrix.sync.aligned.m8n8.x4.shared.b16 {%0,%1,%2,%3}, [%4];"
        : "=r"(r[0]), "=r"(r[1]), "=r"(r[2]), "=r"(r[3]) : "r"(addr));
}
__device__ __forceinline__ void mma16816h(float* c, const uint32_t* a, const uint32_t* b) {
    asm volatile("mma.sync.aligned.m16n8k16.row.col.f32.f16.f16.f32 "
        "{%0,%1,%2,%3}, {%4,%5,%6,%7}, {%8,%9}, {%0,%1,%2,%3};"
        : "+f"(c[0]), "+f"(c[1]), "+f"(c[2]), "+f"(c[3])
        : "r"(a[0]), "r"(a[1]), "r"(a[2]), "r"(a[3]), "r"(b[0]), "r"(b[1]));
}
__device__ __forceinline__ float gelu_exact(float z) {
    return 0.5f * z * (1.0f + erff(z * 0.70710678118654752f));
}

// ---------------- prep kernels ----------------
__global__ void prep_w(const float* __restrict__ W) {
    int p = blockIdx.x * 256 + threadIdx.x;            // pair index < 4096*304
    int idx = p * 2;
    int m = idx / KPAD, k = idx - m * KPAD;
    // GEMM K-index c*3+kk equals flattened W[m][c][kk] for k<600 (W row = 256*3 floats)
    float v0 = (k     < 600) ? W[m * 768 + k]     : 0.0f;
    float v1 = (k + 1 < 600) ? W[m * 768 + k + 1] : 0.0f;
    __half h0 = __float2half_rn(v0);
    __half h1 = __float2half_rn(v1);
    __half2 hh; hh.x = h0; hh.y = h1;
    __half2 ll;
    ll.x = __float2half_rn(v0 - __half2float(h0));
    ll.y = __float2half_rn(v1 - __half2float(h1));
    *(__half2*)&g_Ahi[idx] = hh;
    *(__half2*)&g_Alo[idx] = ll;
}

__global__ void prep_x(const float* __restrict__ x) {
    __shared__ float xs[50][132];
    const int b = blockIdx.y, t0 = blockIdx.x * 128;
    const int tid = threadIdx.x;
    const float* xb = x + (size_t)b * NCH * TLEN;
    const size_t Bbase = ((size_t)b * TLEN + t0) * KPAD;

    // zero K tail [600,608) — 4 half2 per t
    const __half2 z2 = { __float2half_rn(0.0f), __float2half_rn(0.0f) };
    for (int i = tid; i < 128 * 4; i += 256) {
        int tl = i >> 2, k = 600 + (i & 3) * 2;
        *(__half2*)&g_Bh[Bbase + (size_t)tl * KPAD + k] = z2;
    }

    for (int cc = 0; cc < 4; cc++) {
        const int c0 = cc * 50;
        __syncthreads();
        for (int i = tid; i < 50 * 130; i += 256) {
            int r = i / 130, col = i - r * 130;
            int gt = t0 - 1 + col;
            xs[r][col] = (gt >= 0 && gt < TLEN) ? xb[(size_t)(c0 + r) * TLEN + gt] : 0.0f;
        }
        __syncthreads();
        // 150 K-values per t -> 75 pairs, paired 4B stores
        for (int i = tid; i < 128 * 75; i += 256) {
            int tl = i / 75, j = i - tl * 75;
            int dk0 = 2 * j;
            int cl0 = dk0 / 3,       kk0 = dk0 - cl0 * 3;
            int cl1 = (dk0 + 1) / 3, kk1 = (dk0 + 1) - cl1 * 3;
            __half2 hh;
            hh.x = __float2half_rn(xs[cl0][tl + kk0]);
            hh.y = __float2half_rn(xs[cl1][tl + kk1]);
            *(__half2*)&g_Bh[Bbase + (size_t)tl * KPAD + (c0 * 3 + dk0)] = hh;
        }
    }
}

// ---------------- stage copy: 3 matrices x 128 rows x 64B ----------------
__device__ __forceinline__ void copy_stage(uint32_t sb,
        const __half* __restrict__ Ah, const __half* __restrict__ Al,
        const __half* __restrict__ Bh, int k0, int tid) {
    #pragma unroll
    for (int i = 0; i < 2; i++) {
        int v = tid + i * 256;                 // 0..511
        int row = v >> 2, seg = v & 3;
        uint32_t so = row * (RS * 2) + seg * 16;
        size_t g = (size_t)row * KPAD + k0 + seg * 8;
        CPASYNC16(sb + AH_O + so, Ah + g);
        CPASYNC16(sb + AL_O + so, Al + g);
        CPASYNC16(sb + B_O  + so, Bh + g);
    }
}

// ---------------- main HMMA kernel ----------------
__global__ __launch_bounds__(256, 2)
void dsmain(const int* __restrict__ did_arr,
            const float* __restrict__ bias,
            float* __restrict__ out) {
    extern __shared__ __half sm[];
    const uint32_t sbase = s2u(sm);
    const int tid = threadIdx.x, wid = tid >> 5, lane = tid & 31;
    const int wm = wid >> 2, wn = wid & 3;     // warp grid 2(m) x 4(n)
    const int t0 = blockIdx.x * TILE_N, m0 = blockIdx.y * TILE_M, b = blockIdx.z;
    const int did = did_arr[b];

    const __half* Ah = g_Ahi + (size_t)(did * MD + m0) * KPAD;
    const __half* Al = g_Alo + (size_t)(did * MD + m0) * KPAD;
    const __half* Bh = g_Bh  + ((size_t)b * TLEN + t0) * KPAD;

    // per-lane ldmatrix byte offsets (within one matrix tile)
    uint32_t a_off[4], b_off[2];
    {
        int tl = lane >> 3, sub = lane & 7;
        int koff = (tl >> 1) * 8;
        int mrow = wm * 64 + (tl & 1) * 8 + sub;
        #pragma unroll
        for (int mt = 0; mt < 4; mt++)
            a_off[mt] = ((mrow + mt * 16) * RS + koff) * 2;
        int g = lane >> 3;
        int nr = wn * 32 + (lane & 7) + ((g >> 1) * 8);
        int kk = (g & 1) * 8;
        #pragma unroll
        for (int p = 0; p < 2; p++)
            b_off[p] = ((nr + p * 16) * RS + kk) * 2;
    }

    float acc[4][4][4];
    #pragma unroll
    for (int i = 0; i < 4; i++)
        #pragma unroll
        for (int j = 0; j < 4; j++)
            #pragma unroll
            for (int q = 0; q < 4; q++) acc[i][j][q] = 0.0f;

    // prologue: fill 3 stages
    #pragma unroll
    for (int s = 0; s < NSTAGE; s++) {
        copy_stage(sbase + s * STAGE_BYTES, Ah, Al, Bh, s * KCH, tid);
        CP_COMMIT();
    }

    int sidx = 0;
    for (int c = 0; c < NCHUNK; c++) {
        if (c + 2 < NCHUNK)      { CP_WAIT(2); }
        else if (c + 1 < NCHUNK) { CP_WAIT(1); }
        else                     { CP_WAIT(0); }
        __syncthreads();

        const uint32_t sb = sbase + sidx * STAGE_BYTES;
        #pragma unroll
        for (int ks = 0; ks < 2; ks++) {
            const uint32_t kb = ks * 32;      // +16 halfs
            uint32_t bf[2][4], af[4][4];
            #pragma unroll
            for (int p = 0; p < 2; p++)
                ldsm_x4(bf[p], sb + B_O + b_off[p] + kb);
            #pragma unroll
            for (int mt = 0; mt < 4; mt++)
                ldsm_x4(af[mt], sb + AH_O + a_off[mt] + kb);
            #pragma unroll
            for (int mt = 0; mt < 4; mt++)
                #pragma unroll
                for (int nt = 0; nt < 4; nt++)
                    mma16816h(acc[mt][nt], af[mt], &bf[nt >> 1][(nt & 1) * 2]);
            #pragma unroll
            for (int mt = 0; mt < 4; mt++)
                ldsm_x4(af[mt], sb + AL_O + a_off[mt] + kb);   // reuse regs
            #pragma unroll
            for (int mt = 0; mt < 4; mt++)
                #pragma unroll
                for (int nt = 0; nt < 4; nt++)
                    mma16816h(acc[mt][nt], af[mt], &bf[nt >> 1][(nt & 1) * 2]);
        }
        __syncthreads();

        if (c + NSTAGE < NCHUNK) {
            copy_stage(sb, Ah, Al, Bh, (c + NSTAGE) * KCH, tid);
            CP_COMMIT();
        }
        sidx = (sidx == NSTAGE - 1) ? 0 : sidx + 1;
    }

    // ---- epilogue: bias + exact GELU ----
    const float* brow = bias + did * MD + m0 + wm * 64;
    const int rsub = lane >> 2;
    const int csub = (lane & 3) * 2;
    #pragma unroll
    for (int mt = 0; mt < 4; mt++) {
        const float bv0 = brow[mt * 16 + rsub];
        const float bv1 = brow[mt * 16 + rsub + 8];
        float* o0 = out + ((size_t)(b * MD + m0 + wm * 64 + mt * 16 + rsub)) * TLEN
                        + t0 + wn * 32 + csub;
        float* o1 = o0 + 8 * TLEN;
        #pragma unroll
        for (int nt = 0; nt < 4; nt++) {
            float2 p0, p1;
            p0.x = gelu_exact(acc[mt][nt][0] + bv0);
            p0.y = gelu_exact(acc[mt][nt][1] + bv0);
            p1.x = gelu_exact(acc[mt][nt][2] + bv1);
            p1.y = gelu_exact(acc[mt][nt][3] + bv1);
            *(float2*)(o0 + nt * 8) = p0;
            *(float2*)(o1 + nt * 8) = p1;
        }
    }
}

// ---------------- launch ----------------
extern "C" void kernel_launch(void* const* d_in, const int* in_sizes, int n_in,
                              void* d_out, int out_size) {
    const float* x    = (const float*)d_in[0];   // [32, 200, 1024]
    const int*   did  = (const int*)  d_in[1];   // [32]
    const float* W    = (const float*)d_in[2];   // [4096, 256, 3]
    const float* bias = (const float*)d_in[3];   // [4096]
    float*       out  = (float*)d_out;           // [32, 512, 1024]

    cudaFuncSetAttribute(dsmain, cudaFuncAttributeMaxDynamicSharedMemorySize, SMEM_TOTAL);

    prep_w<<<(4096 * KPAD / 2) / 256, 256>>>(W);
    prep_x<<<dim3(TLEN / 128, NB), 256>>>(x);
    dsmain<<<dim3(TLEN / TILE_N, MD / TILE_M, NB), 256, SMEM_TOTAL>>>(did, bias, out);
}

// round 6
// speedup vs baseline: 5.1493x; 1.3294x over previous
#include <cuda_runtime.h>
#include <cuda_fp16.h>
#include <math.h>
#include <stdint.h>

// ---------------- problem constants ----------------
#define NCH   200
#define TLEN  1024
#define MD    512
#define NB    32
#define KPAD  608          // 600 real (200ch*3taps) + 8 zeros = 19 chunks of 32

// ---------------- tiling ----------------
#define TILE_M 128
#define TILE_N 128
#define KCH    32
#define NCHUNK (KPAD / KCH)        // 19
#define NSTAGE 4
#define RS     40                  // smem row stride in halfs (80B, LDSM conflict-free)
#define MAT_B  (128 * RS * 2)      // bytes per matrix tile per stage (10240)
#define A_O    0
#define B_O    MAT_B
#define STAGE_BYTES (2 * MAT_B)            // 20480
#define SMEM_TOTAL  (NSTAGE * STAGE_BYTES) // 81920 -> 2 CTAs/SM

// ---------------- device scratch (bss) ----------------
__device__ __half g_A[4096 * KPAD];
__device__ __half g_B[(size_t)NB * TLEN * KPAD];

// ---------------- PTX helpers (baseline PTX, compute_103-safe) ----------------
__device__ __forceinline__ uint32_t s2u(const void* p) {
    uint32_t a;
    asm("{ .reg .u64 t; cvta.to.shared.u64 t, %1; cvt.u32.u64 %0, t; }" : "=r"(a) : "l"(p));
    return a;
}
#define CPASYNC16(dst, src) \
    asm volatile("cp.async.cg.shared.global [%0], [%1], 16;" :: "r"(dst), "l"(src) : "memory")
#define CP_COMMIT() asm volatile("cp.async.commit_group;" ::: "memory")
#define CP_WAIT(n)  asm volatile("cp.async.wait_group %0;" :: "n"(n) : "memory")

__device__ __forceinline__ void ldsm_x4(uint32_t* r, uint32_t addr) {
    asm volatile("ldmatrix.sync.aligned.m8n8.x4.shared.b16 {%0,%1,%2,%3}, [%4];"
        : "=r"(r[0]), "=r"(r[1]), "=r"(r[2]), "=r"(r[3]) : "r"(addr));
}
__device__ __forceinline__ void mma16816h(float* c, const uint32_t* a, const uint32_t* b) {
    asm volatile("mma.sync.aligned.m16n8k16.row.col.f32.f16.f16.f32 "
        "{%0,%1,%2,%3}, {%4,%5,%6,%7}, {%8,%9}, {%0,%1,%2,%3};"
        : "+f"(c[0]), "+f"(c[1]), "+f"(c[2]), "+f"(c[3])
        : "r"(a[0]), "r"(a[1]), "r"(a[2]), "r"(a[3]), "r"(b[0]), "r"(b[1]));
}
__device__ __forceinline__ float gelu_exact(float z) {
    return 0.5f * z * (1.0f + erff(z * 0.70710678118654752f));
}

// ---------------- prep kernels ----------------
__global__ void prep_w(const float* __restrict__ W) {
    int p = blockIdx.x * 256 + threadIdx.x;            // pair index < 4096*304
    int idx = p * 2;
    int m = idx / KPAD, k = idx - m * KPAD;
    // GEMM K-index c*3+kk equals flattened W[m][c][kk] for k<600 (W row = 256*3 floats)
    float v0 = (k     < 600) ? W[m * 768 + k]     : 0.0f;
    float v1 = (k + 1 < 600) ? W[m * 768 + k + 1] : 0.0f;
    __half2 hh;
    hh.x = __float2half_rn(v0);
    hh.y = __float2half_rn(v1);
    *(__half2*)&g_A[idx] = hh;
}

__global__ void prep_x(const float* __restrict__ x) {
    __shared__ float xs[50][132];
    const int b = blockIdx.y, t0 = blockIdx.x * 128;
    const int tid = threadIdx.x;
    const float* xb = x + (size_t)b * NCH * TLEN;
    const size_t Bbase = ((size_t)b * TLEN + t0) * KPAD;

    // zero K tail [600,608)
    const __half2 z2 = { __float2half_rn(0.0f), __float2half_rn(0.0f) };
    for (int i = tid; i < 128 * 4; i += 256) {
        int tl = i >> 2, k = 600 + (i & 3) * 2;
        *(__half2*)&g_B[Bbase + (size_t)tl * KPAD + k] = z2;
    }

    for (int cc = 0; cc < 4; cc++) {
        const int c0 = cc * 50;
        __syncthreads();
        for (int i = tid; i < 50 * 130; i += 256) {
            int r = i / 130, col = i - r * 130;
            int gt = t0 - 1 + col;
            xs[r][col] = (gt >= 0 && gt < TLEN) ? xb[(size_t)(c0 + r) * TLEN + gt] : 0.0f;
        }
        __syncthreads();
        // 150 K-values per t -> 75 pairs, paired 4B stores
        for (int i = tid; i < 128 * 75; i += 256) {
            int tl = i / 75, j = i - tl * 75;
            int dk0 = 2 * j;
            int cl0 = dk0 / 3,       kk0 = dk0 - cl0 * 3;
            int cl1 = (dk0 + 1) / 3, kk1 = (dk0 + 1) - cl1 * 3;
            __half2 hh;
            hh.x = __float2half_rn(xs[cl0][tl + kk0]);
            hh.y = __float2half_rn(xs[cl1][tl + kk1]);
            *(__half2*)&g_B[Bbase + (size_t)tl * KPAD + (c0 * 3 + dk0)] = hh;
        }
    }
}

// ---------------- stage copy: 2 matrices x 128 rows x 64B ----------------
__device__ __forceinline__ void copy_stage(uint32_t sb,
        const __half* __restrict__ A, const __half* __restrict__ B,
        int k0, int tid) {
    #pragma unroll
    for (int i = 0; i < 2; i++) {
        int v = tid + i * 256;                 // 0..511
        int row = v >> 2, seg = v & 3;
        uint32_t so = row * (RS * 2) + seg * 16;
        size_t g = (size_t)row * KPAD + k0 + seg * 8;
        CPASYNC16(sb + A_O + so, A + g);
        CPASYNC16(sb + B_O + so, B + g);
    }
}

// ---------------- main HMMA kernel ----------------
__global__ __launch_bounds__(256, 2)
void dsmain(const int* __restrict__ did_arr,
            const float* __restrict__ bias,
            float* __restrict__ out) {
    extern __shared__ __half sm[];
    const uint32_t sbase = s2u(sm);
    const int tid = threadIdx.x, wid = tid >> 5, lane = tid & 31;
    const int wm = wid >> 2, wn = wid & 3;     // warp grid 2(m) x 4(n)
    const int t0 = blockIdx.x * TILE_N, m0 = blockIdx.y * TILE_M, b = blockIdx.z;
    const int did = did_arr[b];

    const __half* A = g_A + (size_t)(did * MD + m0) * KPAD;
    const __half* B = g_B + ((size_t)b * TLEN + t0) * KPAD;

    // per-lane ldmatrix byte offsets (within one matrix tile)
    uint32_t a_off[4], b_off[2];
    {
        int tl = lane >> 3, sub = lane & 7;
        int koff = (tl >> 1) * 8;
        int mrow = wm * 64 + (tl & 1) * 8 + sub;
        #pragma unroll
        for (int mt = 0; mt < 4; mt++)
            a_off[mt] = ((mrow + mt * 16) * RS + koff) * 2;
        int g = lane >> 3;
        int nr = wn * 32 + (lane & 7) + ((g >> 1) * 8);
        int kk = (g & 1) * 8;
        #pragma unroll
        for (int p = 0; p < 2; p++)
            b_off[p] = ((nr + p * 16) * RS + kk) * 2;
    }

    float acc[4][4][4];
    #pragma unroll
    for (int i = 0; i < 4; i++)
        #pragma unroll
        for (int j = 0; j < 4; j++)
            #pragma unroll
            for (int q = 0; q < 4; q++) acc[i][j][q] = 0.0f;

    // prologue: fill stages
    #pragma unroll
    for (int s = 0; s < NSTAGE - 1; s++) {
        copy_stage(sbase + s * STAGE_BYTES, A, B, s * KCH, tid);
        CP_COMMIT();
    }

    int sidx = 0;
    for (int c = 0; c < NCHUNK; c++) {
        // issue next copy before waiting (keep NSTAGE-1 groups in flight)
        if (c + NSTAGE - 1 < NCHUNK) {
            copy_stage(sbase + ((c + NSTAGE - 1) % NSTAGE) * STAGE_BYTES,
                       A, B, (c + NSTAGE - 1) * KCH, tid);
            CP_COMMIT();
        }
        if (c + NSTAGE - 1 < NCHUNK)      { CP_WAIT(3); }
        else if (c + NSTAGE - 2 < NCHUNK) { CP_WAIT(2); }
        else if (c + NSTAGE - 3 < NCHUNK) { CP_WAIT(1); }
        else                              { CP_WAIT(0); }
        __syncthreads();

        const uint32_t sb = sbase + sidx * STAGE_BYTES;
        #pragma unroll
        for (int ks = 0; ks < 2; ks++) {
            const uint32_t kb = ks * 32;      // +16 halfs
            uint32_t bf[2][4], af[4][4];
            #pragma unroll
            for (int p = 0; p < 2; p++)
                ldsm_x4(bf[p], sb + B_O + b_off[p] + kb);
            #pragma unroll
            for (int mt = 0; mt < 4; mt++)
                ldsm_x4(af[mt], sb + A_O + a_off[mt] + kb);
            #pragma unroll
            for (int mt = 0; mt < 4; mt++)
                #pragma unroll
                for (int nt = 0; nt < 4; nt++)
                    mma16816h(acc[mt][nt], af[mt], &bf[nt >> 1][(nt & 1) * 2]);
        }
        __syncthreads();
        sidx = (sidx == NSTAGE - 1) ? 0 : sidx + 1;
    }

    // ---- epilogue: bias + exact GELU ----
    const float* brow = bias + did * MD + m0 + wm * 64;
    const int rsub = lane >> 2;
    const int csub = (lane & 3) * 2;
    #pragma unroll
    for (int mt = 0; mt < 4; mt++) {
        const float bv0 = brow[mt * 16 + rsub];
        const float bv1 = brow[mt * 16 + rsub + 8];
        float* o0 = out + ((size_t)(b * MD + m0 + wm * 64 + mt * 16 + rsub)) * TLEN
                        + t0 + wn * 32 + csub;
        float* o1 = o0 + 8 * TLEN;
        #pragma unroll
        for (int nt = 0; nt < 4; nt++) {
            float2 p0, p1;
            p0.x = gelu_exact(acc[mt][nt][0] + bv0);
            p0.y = gelu_exact(acc[mt][nt][1] + bv0);
            p1.x = gelu_exact(acc[mt][nt][2] + bv1);
            p1.y = gelu_exact(acc[mt][nt][3] + bv1);
            *(float2*)(o0 + nt * 8) = p0;
            *(float2*)(o1 + nt * 8) = p1;
        }
    }
}

// ---------------- launch ----------------
extern "C" void kernel_launch(void* const* d_in, const int* in_sizes, int n_in,
                              void* d_out, int out_size) {
    const float* x    = (const float*)d_in[0];   // [32, 200, 1024]
    const int*   did  = (const int*)  d_in[1];   // [32]
    const float* W    = (const float*)d_in[2];   // [4096, 256, 3]
    const float* bias = (const float*)d_in[3];   // [4096]
    float*       out  = (float*)d_out;           // [32, 512, 1024]

    cudaFuncSetAttribute(dsmain, cudaFuncAttributeMaxDynamicSharedMemorySize, SMEM_TOTAL);

    prep_w<<<(4096 * KPAD / 2) / 256, 256>>>(W);
    prep_x<<<dim3(TLEN / 128, NB), 256>>>(x);
    dsmain<<<dim3(TLEN / TILE_N, MD / TILE_M, NB), 256, SMEM_TOTAL>>>(did, bias, out);
}

// round 7
// speedup vs baseline: 5.6597x; 1.0991x over previous
#include <cuda_runtime.h>
#include <cuda_fp16.h>
#include <math.h>
#include <stdint.h>

// ---------------- problem constants ----------------
#define NCH   200
#define TLEN  1024
#define MD    512
#define NB    32
#define KPAD  640          // 600 real (200ch*3taps) + 40 zeros = 10 chunks of 64

// ---------------- tiling ----------------
#define TILE_M 128
#define TILE_N 64
#define KCH    64
#define NCHUNK (KPAD / KCH)        // 10
#define NSTAGE 3
#define RS     72                  // smem row stride in halfs (144B; 9r mod 8 -> LDSM conflict-free)
#define A_O    0
#define A_BYTES (128 * RS * 2)             // 18432
#define B_O    A_BYTES
#define B_BYTES (64 * RS * 2)              // 9216
#define STAGE_BYTES (A_BYTES + B_BYTES)    // 27648
#define SMEM_TOTAL  (NSTAGE * STAGE_BYTES) // 82944 -> 2 CTAs/SM

// ---------------- device scratch (bss) ----------------
__device__ __half g_A[4096 * KPAD];
__device__ __half g_B[(size_t)NB * TLEN * KPAD];

// ---------------- PTX helpers (baseline PTX, compute_103-safe) ----------------
__device__ __forceinline__ uint32_t s2u(const void* p) {
    uint32_t a;
    asm("{ .reg .u64 t; cvta.to.shared.u64 t, %1; cvt.u32.u64 %0, t; }" : "=r"(a) : "l"(p));
    return a;
}
#define CPASYNC16(dst, src) \
    asm volatile("cp.async.cg.shared.global [%0], [%1], 16;" :: "r"(dst), "l"(src) : "memory")
#define CP_COMMIT() asm volatile("cp.async.commit_group;" ::: "memory")
#define CP_WAIT(n)  asm volatile("cp.async.wait_group %0;" :: "n"(n) : "memory")

__device__ __forceinline__ void ldsm_x4(uint32_t* r, uint32_t addr) {
    asm volatile("ldmatrix.sync.aligned.m8n8.x4.shared.b16 {%0,%1,%2,%3}, [%4];"
        : "=r"(r[0]), "=r"(r[1]), "=r"(r[2]), "=r"(r[3]) : "r"(addr));
}
__device__ __forceinline__ void mma16816h(float* c, const uint32_t* a, const uint32_t* b) {
    asm volatile("mma.sync.aligned.m16n8k16.row.col.f32.f16.f16.f32 "
        "{%0,%1,%2,%3}, {%4,%5,%6,%7}, {%8,%9}, {%0,%1,%2,%3};"
        : "+f"(c[0]), "+f"(c[1]), "+f"(c[2]), "+f"(c[3])
        : "r"(a[0]), "r"(a[1]), "r"(a[2]), "r"(a[3]), "r"(b[0]), "r"(b[1]));
}
__device__ __forceinline__ float gelu_exact(float z) {
    return 0.5f * z * (1.0f + erff(z * 0.70710678118654752f));
}

// ---------------- prep kernels ----------------
__global__ void prep_w(const float* __restrict__ W) {
    int p = blockIdx.x * 256 + threadIdx.x;            // quad index < 4096*160
    int idx = p * 4;
    int m = idx / KPAD, k = idx - m * KPAD;
    // GEMM K-index c*3+kk equals flattened W[m][c][kk] for k<600 (W row = 768 floats)
    const float* wr = W + m * 768 + k;
    float v0 = (k     < 600) ? wr[0] : 0.0f;
    float v1 = (k + 1 < 600) ? wr[1] : 0.0f;
    float v2 = (k + 2 < 600) ? wr[2] : 0.0f;
    float v3 = (k + 3 < 600) ? wr[3] : 0.0f;
    __half2 h01, h23;
    h01.x = __float2half_rn(v0); h01.y = __float2half_rn(v1);
    h23.x = __float2half_rn(v2); h23.y = __float2half_rn(v3);
    *(__half2*)&g_A[idx]     = h01;
    *(__half2*)&g_A[idx + 2] = h23;
}

__global__ void prep_x(const float* __restrict__ x) {
    __shared__ float xs[50][68];
    const int b = blockIdx.y, t0 = blockIdx.x * 64;
    const int tid = threadIdx.x;
    const float* xb = x + (size_t)b * NCH * TLEN;
    const size_t Bbase = ((size_t)b * TLEN + t0) * KPAD;

    // zero K tail [600,640): 20 half2 per t
    const __half2 z2 = { __float2half_rn(0.0f), __float2half_rn(0.0f) };
    for (int i = tid; i < 64 * 20; i += 256) {
        int tl = i / 20, q = i - tl * 20;
        *(__half2*)&g_B[Bbase + (size_t)tl * KPAD + 600 + q * 2] = z2;
    }

    for (int cc = 0; cc < 4; cc++) {
        const int c0 = cc * 50;
        __syncthreads();
        for (int i = tid; i < 50 * 66; i += 256) {
            int r = i / 66, col = i - r * 66;
            int gt = t0 - 1 + col;
            xs[r][col] = (gt >= 0 && gt < TLEN) ? xb[(size_t)(c0 + r) * TLEN + gt] : 0.0f;
        }
        __syncthreads();
        // 150 K-values per t -> 75 pairs, half2 stores (c0*3 is even)
        for (int i = tid; i < 64 * 75; i += 256) {
            int tl = i / 75, j = i - tl * 75;
            int dk0 = 2 * j;
            int cl0 = dk0 / 3,       kk0 = dk0 - cl0 * 3;
            int cl1 = (dk0 + 1) / 3, kk1 = (dk0 + 1) - cl1 * 3;
            __half2 hh;
            hh.x = __float2half_rn(xs[cl0][tl + kk0]);
            hh.y = __float2half_rn(xs[cl1][tl + kk1]);
            *(__half2*)&g_B[Bbase + (size_t)tl * KPAD + (c0 * 3 + dk0)] = hh;
        }
    }
}

// ---------------- stage copy: A 128x128B + B 64x128B ----------------
__device__ __forceinline__ void copy_stage(uint32_t sb,
        const __half* __restrict__ A, const __half* __restrict__ B,
        int k0, int tid) {
    #pragma unroll
    for (int i = 0; i < 4; i++) {              // A: 1024 x 16B
        int v = tid + i * 256;
        int row = v >> 3, seg = v & 7;
        CPASYNC16(sb + A_O + row * (RS * 2) + seg * 16,
                  A + (size_t)row * KPAD + k0 + seg * 8);
    }
    #pragma unroll
    for (int i = 0; i < 2; i++) {              // B: 512 x 16B
        int v = tid + i * 256;
        int row = v >> 3, seg = v & 7;
        CPASYNC16(sb + B_O + row * (RS * 2) + seg * 16,
                  B + (size_t)row * KPAD + k0 + seg * 8);
    }
}

// ---------------- main HMMA kernel ----------------
__global__ __launch_bounds__(256, 2)
void dsmain(const int* __restrict__ did_arr,
            const float* __restrict__ bias,
            float* __restrict__ out) {
    extern __shared__ __half sm[];
    const uint32_t sbase = s2u(sm);
    const int tid = threadIdx.x, wid = tid >> 5, lane = tid & 31;
    const int wm = wid >> 2, wn = wid & 3;     // warp grid 2(m,64 rows) x 4(n,16 cols)
    const int t0 = blockIdx.x * TILE_N, m0 = blockIdx.y * TILE_M, b = blockIdx.z;
    const int did = did_arr[b];

    const __half* A = g_A + (size_t)(did * MD + m0) * KPAD;
    const __half* B = g_B + ((size_t)b * TLEN + t0) * KPAD;

    // per-lane ldmatrix byte offsets (within one stage)
    uint32_t a_off[4], b_off;
    {
        int tl = lane >> 3, sub = lane & 7;
        int koff = (tl >> 1) * 8;
        int mrow = wm * 64 + (tl & 1) * 8 + sub;
        #pragma unroll
        for (int mt = 0; mt < 4; mt++)
            a_off[mt] = ((mrow + mt * 16) * RS + koff) * 2;
        int g = lane >> 3;
        int nr = wn * 16 + (lane & 7) + ((g >> 1) * 8);
        int kk = (g & 1) * 8;
        b_off = (nr * RS + kk) * 2;
    }

    float acc[4][2][4];
    #pragma unroll
    for (int i = 0; i < 4; i++)
        #pragma unroll
        for (int j = 0; j < 2; j++)
            #pragma unroll
            for (int q = 0; q < 4; q++) acc[i][j][q] = 0.0f;

    // prologue: fill 2 stages
    copy_stage(sbase,               A, B, 0,   tid); CP_COMMIT();
    copy_stage(sbase + STAGE_BYTES, A, B, KCH, tid); CP_COMMIT();

    int sidx = 0;
    for (int c = 0; c < NCHUNK; c++) {
        if (c == NCHUNK - 1) { CP_WAIT(0); } else { CP_WAIT(1); }
        __syncthreads();   // single barrier: also fences stage (c-1)%3 reuse below

        if (c + 2 < NCHUNK) {
            copy_stage(sbase + ((c + 2) % NSTAGE) * STAGE_BYTES, A, B,
                       (c + 2) * KCH, tid);
            CP_COMMIT();
        }

        const uint32_t sb = sbase + sidx * STAGE_BYTES;
        #pragma unroll
        for (int ks = 0; ks < 4; ks++) {
            const uint32_t kb = ks * 32;       // +16 halfs
            uint32_t bf[4], af[4][4];
            ldsm_x4(bf, sb + B_O + b_off + kb);
            #pragma unroll
            for (int mt = 0; mt < 4; mt++)
                ldsm_x4(af[mt], sb + A_O + a_off[mt] + kb);
            #pragma unroll
            for (int mt = 0; mt < 4; mt++)
                #pragma unroll
                for (int nt = 0; nt < 2; nt++)
                    mma16816h(acc[mt][nt], af[mt], &bf[nt * 2]);
        }
        sidx = (sidx == NSTAGE - 1) ? 0 : sidx + 1;
    }

    // ---- epilogue: bias + exact GELU ----
    const float* brow = bias + did * MD + m0 + wm * 64;
    const int rsub = lane >> 2;
    const int csub = (lane & 3) * 2;
    #pragma unroll
    for (int mt = 0; mt < 4; mt++) {
        const float bv0 = brow[mt * 16 + rsub];
        const float bv1 = brow[mt * 16 + rsub + 8];
        float* o0 = out + ((size_t)(b * MD + m0 + wm * 64 + mt * 16 + rsub)) * TLEN
                        + t0 + wn * 16 + csub;
        float* o1 = o0 + 8 * TLEN;
        #pragma unroll
        for (int nt = 0; nt < 2; nt++) {
            float2 p0, p1;
            p0.x = gelu_exact(acc[mt][nt][0] + bv0);
            p0.y = gelu_exact(acc[mt][nt][1] + bv0);
            p1.x = gelu_exact(acc[mt][nt][2] + bv1);
            p1.y = gelu_exact(acc[mt][nt][3] + bv1);
            *(float2*)(o0 + nt * 8) = p0;
            *(float2*)(o1 + nt * 8) = p1;
        }
    }
}

// ---------------- launch ----------------
extern "C" void kernel_launch(void* const* d_in, const int* in_sizes, int n_in,
                              void* d_out, int out_size) {
    const float* x    = (const float*)d_in[0];   // [32, 200, 1024]
    const int*   did  = (const int*)  d_in[1];   // [32]
    const float* W    = (const float*)d_in[2];   // [4096, 256, 3]
    const float* bias = (const float*)d_in[3];   // [4096]
    float*       out  = (float*)d_out;           // [32, 512, 1024]

    cudaFuncSetAttribute(dsmain, cudaFuncAttributeMaxDynamicSharedMemorySize, SMEM_TOTAL);

    prep_w<<<(4096 * KPAD / 4) / 256, 256>>>(W);
    prep_x<<<dim3(TLEN / 64, NB), 256>>>(x);
    dsmain<<<dim3(TLEN / TILE_N, MD / TILE_M, NB), 256, SMEM_TOTAL>>>(did, bias, out);
}